// round 2
// baseline (speedup 1.0000x reference)
#include <cuda_runtime.h>
#include <math.h>

#define BB 256
#define TT 128
#define DD 64
#define HH 512
#define AA 128
#define OO 32
#define NCAT 1536   // packed gate|dyn|tau columns

// ---------------- device scratch (no allocs allowed) ----------------------
__device__ float g_K[BB * TT * AA];
__device__ float g_V[BB * TT * AA];
__device__ float g_Wpack[HH * NCAT];
__device__ float g_base[BB * 1024];
__device__ float g_ctx[BB * AA];
__device__ float g_h[BB * HH];
__device__ float g_hsA[BB * HH];
__device__ float g_hsB[BB * HH];
__device__ float g_k1[BB * HH];
__device__ float g_k2[BB * HH];
__device__ float g_k3[BB * HH];
__device__ float g_leak[HH];

__device__ __forceinline__ float softplusf(float x) {
    return (x > 20.f) ? x : log1pf(expf(x));
}
__device__ __forceinline__ float sigmoidf(float x) {
    return 1.f / (1.f + expf(-x));
}

// ---------------- prep: leak vector + zero h --------------------------------
__global__ void k_prep(const float* __restrict__ cm, const float* __restrict__ gleak) {
    int i = blockIdx.x * 256 + threadIdx.x;
    if (i < HH) g_leak[i] = softplusf(cm[i]) + softplusf(gleak[i]);
    if (i < BB * HH) g_h[i] = 0.f;
}

// ---------------- pack [W_gd_h | W_tau] into (gate,dyn,tau) col groups ------
// Wpack[k][g*96+c]: c<32 gate col g*32+c ; c<64 dyn col 512+g*32+(c-32) ;
//                   c<96 tau col g*32+(c-64) of W_tau.
__global__ void k_pack(const float* __restrict__ W_gd, const float* __restrict__ W_tau) {
    int j = blockIdx.x * 256 + threadIdx.x;       // < 512*1536
    int k = j / NCAT, n = j - k * NCAT;
    int g = n / 96, c = n - g * 96;
    float v;
    if (c < 32)      v = W_gd[(64 + k) * 1024 + g * 32 + c];
    else if (c < 64) v = W_gd[(64 + k) * 1024 + 512 + g * 32 + (c - 32)];
    else             v = W_tau[k * 512 + g * 32 + (c - 64)];
    g_Wpack[j] = v;
}

// ---------------- K/V row t-1 from current g_h ------------------------------
// GEMM M=256 x N=256 (K cols 0..127, V cols 128..255) x K=512.
__global__ void k_kv(int t, const float* __restrict__ Wk, const float* __restrict__ bk,
                     const float* __restrict__ Wv, const float* __restrict__ bv) {
    __shared__ float Ah[64][36];
    int nt = blockIdx.x, mt = blockIdx.y;
    int b0 = mt * 32;
    int tid = threadIdx.x;                 // 256
    int tx = tid & 31;                     // local n
    int ty = tid >> 5;                     // 0..7 -> rows ty*4..ty*4+3
    int n = nt * 32 + tx;
    const float* W = (n < 128) ? Wk : Wv;
    int ncol = n & 127;
    float a0 = 0.f, a1 = 0.f, a2 = 0.f, a3 = 0.f;
    for (int kk = 0; kk < HH; kk += 64) {
        int lm = tid >> 4;                 // 0..15
        int lk = (tid & 15) * 4;           // 0..60
#pragma unroll
        for (int r = 0; r < 2; r++) {
            float4 v = *(const float4*)&g_h[(b0 + lm + 16 * r) * HH + kk + lk];
            Ah[lk + 0][lm + 16 * r] = v.x;
            Ah[lk + 1][lm + 16 * r] = v.y;
            Ah[lk + 2][lm + 16 * r] = v.z;
            Ah[lk + 3][lm + 16 * r] = v.w;
        }
        __syncthreads();
#pragma unroll 16
        for (int k = 0; k < 64; k++) {
            float w = W[(kk + k) * AA + ncol];
            float4 av = *(const float4*)&Ah[k][ty * 4];
            a0 += av.x * w; a1 += av.y * w; a2 += av.z * w; a3 += av.w * w;
        }
        __syncthreads();
    }
    float bias = (n < 128) ? bk[ncol] : bv[ncol];
    float* dst = (n < 128) ? g_K : g_V;
    int row = t - 1;
    dst[((b0 + ty * 4 + 0) * TT + row) * AA + ncol] = a0 + bias;
    dst[((b0 + ty * 4 + 1) * TT + row) * AA + ncol] = a1 + bias;
    dst[((b0 + ty * 4 + 2) * TT + row) * AA + ncol] = a2 + bias;
    dst[((b0 + ty * 4 + 3) * TT + row) * AA + ncol] = a3 + bias;
}

// ---------------- attention: Q inline, softmax, ctx; one block per batch ----
__global__ void k_attn(int t, const float* __restrict__ x,
                       const float* __restrict__ Wq, const float* __restrict__ bq) {
    int b = blockIdx.x;
    int tid = threadIdx.x;                 // 128
    if (t == 0) { g_ctx[b * AA + tid] = 0.f; return; }
    __shared__ float q[AA];
    __shared__ float sc[TT];
    __shared__ float red[4];
    if (tid < DD) sc[tid] = x[(b * TT + t) * DD + tid];
    __syncthreads();
    float acc = bq[tid];
#pragma unroll 16
    for (int d = 0; d < DD; d++) acc += sc[d] * Wq[d * AA + tid];
    q[tid] = acc;
    __syncthreads();
    float s = -1e30f;
    if (tid < t) {
        const float4* Kp = (const float4*)&g_K[(b * TT + tid) * AA];
        float dot = 0.f;
#pragma unroll 8
        for (int a4 = 0; a4 < AA / 4; a4++) {
            float4 kv = Kp[a4];
            dot += kv.x * q[4 * a4] + kv.y * q[4 * a4 + 1] +
                   kv.z * q[4 * a4 + 2] + kv.w * q[4 * a4 + 3];
        }
        s = dot * (1.f / 11.313708498984761f);   // 1/sqrt(128)
    }
    float m = s;
#pragma unroll
    for (int o = 16; o > 0; o >>= 1) m = fmaxf(m, __shfl_xor_sync(0xffffffffu, m, o));
    if ((tid & 31) == 0) red[tid >> 5] = m;
    __syncthreads();
    m = fmaxf(fmaxf(red[0], red[1]), fmaxf(red[2], red[3]));
    float e = (tid < t) ? expf(s - m) : 0.f;
    float sum = e;
#pragma unroll
    for (int o = 16; o > 0; o >>= 1) sum += __shfl_xor_sync(0xffffffffu, sum, o);
    __syncthreads();
    if ((tid & 31) == 0) red[tid >> 5] = sum;
    __syncthreads();
    sum = red[0] + red[1] + red[2] + red[3];
    sc[tid] = e / sum;
    __syncthreads();
    float c = 0.f;
    for (int sx = 0; sx < t; sx++)
        c += sc[sx] * g_V[(b * TT + sx) * AA + tid];
    g_ctx[b * AA + tid] = c;
}

// ---------------- base = b_gd + x_t@W_gd_x + ctx@W_gd_ctx --------------------
// GEMM M=256 x N=1024 x K=192 (K fully staged in smem).
__global__ void k_base(int t, const float* __restrict__ x_states,
                       const float* __restrict__ W_gd, const float* __restrict__ b_gd) {
    __shared__ float As[192][36];
    int jt = blockIdx.x, mt = blockIdx.y;
    int b0 = mt * 32;
    int tid = threadIdx.x;                 // 256
#pragma unroll
    for (int i = 0; i < 24; i++) {
        int idx = i * 256 + tid;           // < 6144
        int bl = idx / 192, k = idx - bl * 192;
        float v = (k < 64) ? x_states[((b0 + bl) * TT + t) * DD + k]
                           : g_ctx[(b0 + bl) * AA + (k - 64)];
        As[k][bl] = v;
    }
    __syncthreads();
    int tx = tid & 63;                     // local j
    int ty = tid >> 6;                     // 0..3 -> rows ty*8..ty*8+7
    int j = jt * 64 + tx;
    float acc[8];
#pragma unroll
    for (int r = 0; r < 8; r++) acc[r] = 0.f;
#pragma unroll 4
    for (int k = 0; k < 64; k++) {
        float w = W_gd[k * 1024 + j];
        float4 v0 = *(const float4*)&As[k][ty * 8];
        float4 v1 = *(const float4*)&As[k][ty * 8 + 4];
        acc[0] += v0.x * w; acc[1] += v0.y * w; acc[2] += v0.z * w; acc[3] += v0.w * w;
        acc[4] += v1.x * w; acc[5] += v1.y * w; acc[6] += v1.z * w; acc[7] += v1.w * w;
    }
#pragma unroll 4
    for (int k = 64; k < 192; k++) {
        float w = W_gd[(k + 512) * 1024 + j];   // ctx rows 576..703
        float4 v0 = *(const float4*)&As[k][ty * 8];
        float4 v1 = *(const float4*)&As[k][ty * 8 + 4];
        acc[0] += v0.x * w; acc[1] += v0.y * w; acc[2] += v0.z * w; acc[3] += v0.w * w;
        acc[4] += v1.x * w; acc[5] += v1.y * w; acc[6] += v1.z * w; acc[7] += v1.w * w;
    }
    float bg = b_gd[j];
#pragma unroll
    for (int r = 0; r < 8; r++)
        g_base[(b0 + ty * 8 + r) * 1024 + j] = acc[r] + bg;
}

// ---------------- RK stage GEMM z = h_s @ Wpack, fused nonlinearity ---------
// grid (16 h-groups, 8 m-tiles), 128 threads, block tile 32m x 96n, thread 4x6.
__global__ void __launch_bounds__(128) k_stage(int t, int stage,
                                               const float* __restrict__ b_tau,
                                               const float* __restrict__ x_dts) {
    __shared__ float As[32][36];
    __shared__ float Bs[32][104];          // also reused as z spill buffer
    int g  = blockIdx.x;                   // h group 0..15
    int mt = blockIdx.y;
    int m0 = mt * 32;
    int tid = threadIdx.x;
    const float* A = (stage == 0) ? g_h : ((stage == 2) ? g_hsB : g_hsA);
    int tx = tid & 15;                     // cols tx*6..tx*6+5
    int ty = tid >> 4;                     // 0..7 -> rows ty*4..ty*4+3
    float acc[4][6];
#pragma unroll
    for (int i = 0; i < 4; i++)
#pragma unroll
        for (int jx = 0; jx < 6; jx++) acc[i][jx] = 0.f;

    int lmA = tid >> 3;                    // 0..15
    int lkA = (tid & 7) << 2;              // 0..28
    int lkB = tid >> 2;                    // 0..31
    int lcB = tid & 3;                     // 0..3
    const float* Bbase = &g_Wpack[g * 96];

    for (int kk = 0; kk < HH; kk += 32) {
#pragma unroll
        for (int r = 0; r < 2; r++) {
            float4 v = *(const float4*)&A[(m0 + lmA + 16 * r) * HH + kk + lkA];
            As[lkA + 0][lmA + 16 * r] = v.x;
            As[lkA + 1][lmA + 16 * r] = v.y;
            As[lkA + 2][lmA + 16 * r] = v.z;
            As[lkA + 3][lmA + 16 * r] = v.w;
        }
        const float* Brow = Bbase + (kk + lkB) * NCAT;
#pragma unroll
        for (int p = 0; p < 6; p++) {
            int c = (lcB + 4 * p) * 4;
            *(float4*)&Bs[lkB][c] = *(const float4*)&Brow[c];
        }
        __syncthreads();
#pragma unroll
        for (int k = 0; k < 32; k++) {
            float4 av = *(const float4*)&As[k][ty * 4];
            float2 b0 = *(const float2*)&Bs[k][tx * 6];
            float2 b1 = *(const float2*)&Bs[k][tx * 6 + 2];
            float2 b2 = *(const float2*)&Bs[k][tx * 6 + 4];
            float aa[4] = {av.x, av.y, av.z, av.w};
            float bb[6] = {b0.x, b0.y, b1.x, b1.y, b2.x, b2.y};
#pragma unroll
            for (int i = 0; i < 4; i++)
#pragma unroll
                for (int jx = 0; jx < 6; jx++)
                    acc[i][jx] += aa[i] * bb[jx];
        }
        __syncthreads();
    }

    // spill z tile (32b x 96n) into smem so epilogue can gather (gate,dyn,tau)
    float* zb = &Bs[0][0];                 // 3072 floats <= 3328
#pragma unroll
    for (int i = 0; i < 4; i++)
#pragma unroll
        for (int jx = 0; jx < 6; jx++)
            zb[(ty * 4 + i) * 96 + tx * 6 + jx] = acc[i][jx];
    __syncthreads();

    int h0 = g * 32;
#pragma unroll
    for (int p = 0; p < 8; p++) {
        int idx = p * 128 + tid;           // 0..1023
        int bl = idx >> 5, hh = idx & 31;
        int b = m0 + bl, h = h0 + hh;
        int gi = b * HH + h;
        float gate = zb[bl * 96 + hh]      + g_base[b * 1024 + h];
        float dyn  = zb[bl * 96 + 32 + hh] + g_base[b * 1024 + 512 + h];
        float tau  = softplusf(zb[bl * 96 + 64 + hh] + b_tau[h]);
        float hsv  = A[gi];
        float kd   = (sigmoidf(gate) * tanhf(dyn) - hsv) / (tau + g_leak[h] + 1e-6f);
        float dt   = x_dts[b * TT + t];
        if (stage == 0) {
            g_k1[gi]  = kd;
            g_hsA[gi] = hsv + dt * kd * (1.f / 3.f);
        } else if (stage == 1) {
            g_k2[gi]  = kd;
            g_hsB[gi] = g_h[gi] + dt * (kd - g_k1[gi] * (1.f / 3.f));
        } else if (stage == 2) {
            g_k3[gi]  = kd;
            g_hsA[gi] = g_h[gi] + dt * (g_k1[gi] - g_k2[gi] + kd);
        } else {
            g_h[gi] = g_h[gi] + dt * (g_k1[gi] + 3.f * g_k2[gi] + 3.f * g_k3[gi] + kd) * 0.125f;
        }
    }
}

// ---------------- final projection: out = h @ W_fc + b_fc -------------------
__global__ void k_final(const float* __restrict__ W_fc, const float* __restrict__ b_fc,
                        float* __restrict__ out) {
    int b = blockIdx.x, o = threadIdx.x;   // 256 blocks x 32 threads
    float acc = b_fc[o];
#pragma unroll 8
    for (int k = 0; k < HH; k++) acc += g_h[b * HH + k] * W_fc[k * OO + o];
    out[b * OO + o] = acc;
}

// ---------------- launch -----------------------------------------------------
extern "C" void kernel_launch(void* const* d_in, const int* in_sizes, int n_in,
                              void* d_out, int out_size) {
    const float* x_states = (const float*)d_in[0];
    const float* x_dts    = (const float*)d_in[1];
    const float* Wq    = (const float*)d_in[2];
    const float* bq    = (const float*)d_in[3];
    const float* Wk    = (const float*)d_in[4];
    const float* bk    = (const float*)d_in[5];
    const float* Wv    = (const float*)d_in[6];
    const float* bv    = (const float*)d_in[7];
    const float* W_gd  = (const float*)d_in[8];
    const float* b_gd  = (const float*)d_in[9];
    const float* W_tau = (const float*)d_in[10];
    const float* b_tau = (const float*)d_in[11];
    const float* gleak = (const float*)d_in[12];
    const float* cm    = (const float*)d_in[13];
    const float* W_fc  = (const float*)d_in[14];
    const float* b_fc  = (const float*)d_in[15];
    float* out = (float*)d_out;

    k_prep<<<512, 256>>>(cm, gleak);
    k_pack<<<3072, 256>>>(W_gd, W_tau);
    for (int t = 0; t < TT; t++) {
        if (t > 0) k_kv<<<dim3(8, 8), 256>>>(t, Wk, bk, Wv, bv);
        k_attn<<<256, 128>>>(t, x_states, Wq, bq);
        k_base<<<dim3(16, 8), 256>>>(t, x_states, W_gd, b_gd);
        for (int s = 0; s < 4; s++)
            k_stage<<<dim3(16, 8), 128>>>(t, s, b_tau, x_dts);
    }
    k_final<<<256, 32>>>(W_fc, b_fc, out);
}

// round 3
// speedup vs baseline: 1.0611x; 1.0611x over previous
#include <cuda_runtime.h>
#include <math.h>
#include <stdint.h>

#define BB 256
#define TT 128
#define DD 64
#define HH 512
#define AA 128
#define OO 32
#define NCAT 1536   // packed gate|dyn|tau columns

// ---------------- device scratch (no allocs allowed) ----------------------
__device__ float g_K[BB * TT * AA];
__device__ float g_V[BB * TT * AA];
__device__ float g_WpackHi[HH * NCAT];   // tf32-rounded high part
__device__ float g_WpackLo[HH * NCAT];   // tf32 residual
__device__ float g_base[BB * 1024];
__device__ float g_ctx[BB * AA];
__device__ float g_h[BB * HH];
__device__ float g_hsA[BB * HH];
__device__ float g_hsB[BB * HH];
__device__ float g_k1[BB * HH];
__device__ float g_k2[BB * HH];
__device__ float g_k3[BB * HH];
__device__ float g_leak[HH];

__device__ __forceinline__ float softplusf(float x) {
    return (x > 20.f) ? x : log1pf(expf(x));
}
__device__ __forceinline__ float sigmoidf(float x) {
    return 1.f / (1.f + expf(-x));
}
__device__ __forceinline__ float f2tf32(float x) {
    uint32_t u;
    asm("cvt.rna.tf32.f32 %0, %1;" : "=r"(u) : "f"(x));
    return __uint_as_float(u);
}
__device__ __forceinline__ void mma8(float* d, const uint32_t* a, const uint32_t* b) {
    asm volatile(
        "mma.sync.aligned.m16n8k8.row.col.f32.tf32.tf32.f32 "
        "{%0,%1,%2,%3},{%4,%5,%6,%7},{%8,%9},{%0,%1,%2,%3};"
        : "+f"(d[0]), "+f"(d[1]), "+f"(d[2]), "+f"(d[3])
        : "r"(a[0]), "r"(a[1]), "r"(a[2]), "r"(a[3]), "r"(b[0]), "r"(b[1]));
}

// ---------------- prep: leak vector + zero h --------------------------------
__global__ void k_prep(const float* __restrict__ cm, const float* __restrict__ gleak) {
    int i = blockIdx.x * 256 + threadIdx.x;
    if (i < HH) g_leak[i] = softplusf(cm[i]) + softplusf(gleak[i]);
    if (i < BB * HH) g_h[i] = 0.f;
}

// ---------------- pack [W_gd_h | W_tau] -> tf32 hi/lo, (gate,dyn,tau) groups
__global__ void k_pack(const float* __restrict__ W_gd, const float* __restrict__ W_tau) {
    int j = blockIdx.x * 256 + threadIdx.x;       // < 512*1536
    int k = j / NCAT, n = j - k * NCAT;
    int g = n / 96, c = n - g * 96;
    float v;
    if (c < 32)      v = W_gd[(64 + k) * 1024 + g * 32 + c];
    else if (c < 64) v = W_gd[(64 + k) * 1024 + 512 + g * 32 + (c - 32)];
    else             v = W_tau[k * 512 + g * 32 + (c - 64)];
    float hi = f2tf32(v);
    g_WpackHi[j] = hi;
    g_WpackLo[j] = f2tf32(v - hi);
}

// ---------------- K/V row t-1 from current g_h ------------------------------
__global__ void k_kv(int t, const float* __restrict__ Wk, const float* __restrict__ bk,
                     const float* __restrict__ Wv, const float* __restrict__ bv) {
    __shared__ float Ah[64][36];
    int nt = blockIdx.x, mt = blockIdx.y;
    int b0 = mt * 32;
    int tid = threadIdx.x;                 // 256
    int tx = tid & 31;
    int ty = tid >> 5;
    int n = nt * 32 + tx;
    const float* W = (n < 128) ? Wk : Wv;
    int ncol = n & 127;
    float a0 = 0.f, a1 = 0.f, a2 = 0.f, a3 = 0.f;
    for (int kk = 0; kk < HH; kk += 64) {
        int lm = tid >> 4;
        int lk = (tid & 15) * 4;
#pragma unroll
        for (int r = 0; r < 2; r++) {
            float4 v = *(const float4*)&g_h[(b0 + lm + 16 * r) * HH + kk + lk];
            Ah[lk + 0][lm + 16 * r] = v.x;
            Ah[lk + 1][lm + 16 * r] = v.y;
            Ah[lk + 2][lm + 16 * r] = v.z;
            Ah[lk + 3][lm + 16 * r] = v.w;
        }
        __syncthreads();
#pragma unroll 16
        for (int k = 0; k < 64; k++) {
            float w = W[(kk + k) * AA + ncol];
            float4 av = *(const float4*)&Ah[k][ty * 4];
            a0 += av.x * w; a1 += av.y * w; a2 += av.z * w; a3 += av.w * w;
        }
        __syncthreads();
    }
    float bias = (n < 128) ? bk[ncol] : bv[ncol];
    float* dst = (n < 128) ? g_K : g_V;
    int row = t - 1;
    dst[((b0 + ty * 4 + 0) * TT + row) * AA + ncol] = a0 + bias;
    dst[((b0 + ty * 4 + 1) * TT + row) * AA + ncol] = a1 + bias;
    dst[((b0 + ty * 4 + 2) * TT + row) * AA + ncol] = a2 + bias;
    dst[((b0 + ty * 4 + 3) * TT + row) * AA + ncol] = a3 + bias;
}

// ---------------- attention: Q inline, softmax, ctx; one block per batch ----
__global__ void k_attn(int t, const float* __restrict__ x,
                       const float* __restrict__ Wq, const float* __restrict__ bq) {
    int b = blockIdx.x;
    int tid = threadIdx.x;                 // 128
    if (t == 0) { g_ctx[b * AA + tid] = 0.f; return; }
    __shared__ float q[AA];
    __shared__ float sc[TT];
    __shared__ float red[4];
    if (tid < DD) sc[tid] = x[(b * TT + t) * DD + tid];
    __syncthreads();
    float acc = bq[tid];
#pragma unroll 16
    for (int d = 0; d < DD; d++) acc += sc[d] * Wq[d * AA + tid];
    q[tid] = acc;
    __syncthreads();
    float s = -1e30f;
    if (tid < t) {
        const float4* Kp = (const float4*)&g_K[(b * TT + tid) * AA];
        float dot = 0.f;
#pragma unroll 8
        for (int a4 = 0; a4 < AA / 4; a4++) {
            float4 kv = Kp[a4];
            dot += kv.x * q[4 * a4] + kv.y * q[4 * a4 + 1] +
                   kv.z * q[4 * a4 + 2] + kv.w * q[4 * a4 + 3];
        }
        s = dot * (1.f / 11.313708498984761f);
    }
    float m = s;
#pragma unroll
    for (int o = 16; o > 0; o >>= 1) m = fmaxf(m, __shfl_xor_sync(0xffffffffu, m, o));
    if ((tid & 31) == 0) red[tid >> 5] = m;
    __syncthreads();
    m = fmaxf(fmaxf(red[0], red[1]), fmaxf(red[2], red[3]));
    float e = (tid < t) ? expf(s - m) : 0.f;
    float sum = e;
#pragma unroll
    for (int o = 16; o > 0; o >>= 1) sum += __shfl_xor_sync(0xffffffffu, sum, o);
    __syncthreads();
    if ((tid & 31) == 0) red[tid >> 5] = sum;
    __syncthreads();
    sum = red[0] + red[1] + red[2] + red[3];
    sc[tid] = e / sum;
    __syncthreads();
    float c = 0.f;
    for (int sx = 0; sx < t; sx++)
        c += sc[sx] * g_V[(b * TT + sx) * AA + tid];
    g_ctx[b * AA + tid] = c;
}

// ---------------- base = b_gd + x_t@W_gd_x + ctx@W_gd_ctx --------------------
// M=256 x N=1024 x K=192. Tile 16m x 128n, W staged via smem chunks.
// grid (8 jt, 16 mt), 256 threads, thread tile 2m x 4n.
__global__ void __launch_bounds__(256) k_base(int t, const float* __restrict__ x_states,
                       const float* __restrict__ W_gd, const float* __restrict__ b_gd) {
    __shared__ float As[192][18];       // [k][m_local]
    __shared__ float Ws[32][132];       // [k_local][n_local]
    int jt = blockIdx.x, mt = blockIdx.y;
    int b0 = mt * 16;
    int j0 = jt * 128;
    int tid = threadIdx.x;
    // stage A (16 rows x 192 k)
#pragma unroll
    for (int i = 0; i < 12; i++) {
        int idx = i * 256 + tid;            // < 3072
        int bl = idx / 192, k = idx - bl * 192;
        float v = (k < 64) ? x_states[((b0 + bl) * TT + t) * DD + k]
                           : g_ctx[(b0 + bl) * AA + (k - 64)];
        As[k][bl] = v;
    }
    int tx = tid & 31;                      // n quad: cols tx*4..+3
    int ty = tid >> 5;                      // 0..7 -> rows ty*2, ty*2+1
    float acc[2][4];
#pragma unroll
    for (int i = 0; i < 2; i++)
#pragma unroll
        for (int jx = 0; jx < 4; jx++) acc[i][jx] = 0.f;

    int wrow = tid >> 3;                    // 0..31
    int wc0  = (tid & 7) * 4;               // 0..28
    for (int kc = 0; kc < 6; kc++) {
        int kbase = kc * 32;
        __syncthreads();
        // stage W chunk: rows kbase..kbase+31, cols j0..j0+127
#pragma unroll
        for (int p = 0; p < 4; p++) {
            int col = wc0 + p * 32;
            int krow = kbase + wrow;
            int wr = (krow < 64) ? krow : krow + 512;
            *(float4*)&Ws[wrow][col] = *(const float4*)&W_gd[wr * 1024 + j0 + col];
        }
        __syncthreads();
#pragma unroll 8
        for (int k = 0; k < 32; k++) {
            float a0 = As[kbase + k][ty * 2];
            float a1 = As[kbase + k][ty * 2 + 1];
            float4 w = *(const float4*)&Ws[k][tx * 4];
            acc[0][0] += a0 * w.x; acc[0][1] += a0 * w.y;
            acc[0][2] += a0 * w.z; acc[0][3] += a0 * w.w;
            acc[1][0] += a1 * w.x; acc[1][1] += a1 * w.y;
            acc[1][2] += a1 * w.z; acc[1][3] += a1 * w.w;
        }
    }
#pragma unroll
    for (int i = 0; i < 2; i++) {
        int b = b0 + ty * 2 + i;
#pragma unroll
        for (int jx = 0; jx < 4; jx++) {
            int j = j0 + tx * 4 + jx;
            g_base[b * 1024 + j] = acc[i][jx] + b_gd[j];
        }
    }
}

// ---------------- RK stage GEMM via 3xTF32 mma.sync, fused nonlinearity -----
// C[256x1536] = A[256x512] @ Wpack. Block tile 32m x 96n, 4 warps (2m x 2n),
// warp tile 16x48 = 6 n-subtiles of m16n8k8. grid (16 hgroups, 8 mtiles).
#define PKA 36
#define PKB 104
__global__ void __launch_bounds__(128) k_stage(int t, int stage,
                                               const float* __restrict__ b_tau,
                                               const float* __restrict__ x_dts) {
    __shared__ float AsHi[32][PKA], AsLo[32][PKA];   // [m][k]
    __shared__ float BsHi[32][PKB], BsLo[32][PKB];   // [k][n]
    int g  = blockIdx.x;
    int mt = blockIdx.y;
    int m0 = mt * 32;
    int tid  = threadIdx.x;
    int lane = tid & 31;
    int wid  = tid >> 5;
    int wm = (wid >> 1) * 16;     // warp m offset within tile
    int wn = (wid & 1) * 48;      // warp n offset
    const float* Ag = (stage == 0) ? g_h : ((stage == 2) ? g_hsB : g_hsA);

    float acc[6][4];
#pragma unroll
    for (int s = 0; s < 6; s++)
#pragma unroll
        for (int i = 0; i < 4; i++) acc[s][i] = 0.f;

    int lmA = tid >> 3;                 // 0..15
    int lkA = (tid & 7) * 4;            // 0..28
    int lkB = tid >> 2;                 // 0..31
    int lcB = tid & 3;                  // 0..3
    const float* BH = &g_WpackHi[g * 96];
    const float* BL = &g_WpackLo[g * 96];

    int ar = wm + (lane >> 2);
    int aq = lane & 3;
    int bg = lane >> 2;

    for (int kk = 0; kk < HH; kk += 32) {
        // stage A hi/lo: 32m x 32k
#pragma unroll
        for (int r = 0; r < 2; r++) {
            int m = lmA + 16 * r;
            float4 v = *(const float4*)&Ag[(m0 + m) * HH + kk + lkA];
            float hx = f2tf32(v.x), hy = f2tf32(v.y), hz = f2tf32(v.z), hw = f2tf32(v.w);
            *(float4*)&AsHi[m][lkA] = make_float4(hx, hy, hz, hw);
            *(float4*)&AsLo[m][lkA] = make_float4(f2tf32(v.x - hx), f2tf32(v.y - hy),
                                                  f2tf32(v.z - hz), f2tf32(v.w - hw));
        }
        // stage B hi/lo: 32k x 96n
        const float* bh = BH + (kk + lkB) * NCAT;
        const float* bl = BL + (kk + lkB) * NCAT;
#pragma unroll
        for (int p = 0; p < 6; p++) {
            int c = (lcB + 4 * p) * 4;
            *(float4*)&BsHi[lkB][c] = *(const float4*)&bh[c];
            *(float4*)&BsLo[lkB][c] = *(const float4*)&bl[c];
        }
        __syncthreads();
#pragma unroll
        for (int q = 0; q < 4; q++) {
            int kb = q * 8;
            uint32_t ahi[4], alo[4];
            ahi[0] = __float_as_uint(AsHi[ar][kb + aq]);
            ahi[1] = __float_as_uint(AsHi[ar + 8][kb + aq]);
            ahi[2] = __float_as_uint(AsHi[ar][kb + aq + 4]);
            ahi[3] = __float_as_uint(AsHi[ar + 8][kb + aq + 4]);
            alo[0] = __float_as_uint(AsLo[ar][kb + aq]);
            alo[1] = __float_as_uint(AsLo[ar + 8][kb + aq]);
            alo[2] = __float_as_uint(AsLo[ar][kb + aq + 4]);
            alo[3] = __float_as_uint(AsLo[ar + 8][kb + aq + 4]);
#pragma unroll
            for (int s = 0; s < 6; s++) {
                int bc = wn + s * 8 + bg;
                int br = kb + aq;
                uint32_t bhi[2], blo[2];
                bhi[0] = __float_as_uint(BsHi[br][bc]);
                bhi[1] = __float_as_uint(BsHi[br + 4][bc]);
                blo[0] = __float_as_uint(BsLo[br][bc]);
                blo[1] = __float_as_uint(BsLo[br + 4][bc]);
                mma8(acc[s], ahi, bhi);
                mma8(acc[s], ahi, blo);
                mma8(acc[s], alo, bhi);
            }
        }
        __syncthreads();
    }

    // spill C tile (32x96) into smem (reuse BsHi), then fused RK epilogue
    float* zb = &BsHi[0][0];
    {
        int r0 = wm + (lane >> 2);
        int c0 = wn + (lane & 3) * 2;
#pragma unroll
        for (int s = 0; s < 6; s++) {
            zb[ r0      * 96 + c0 + s * 8]     = acc[s][0];
            zb[ r0      * 96 + c0 + s * 8 + 1] = acc[s][1];
            zb[(r0 + 8) * 96 + c0 + s * 8]     = acc[s][2];
            zb[(r0 + 8) * 96 + c0 + s * 8 + 1] = acc[s][3];
        }
    }
    __syncthreads();

    int h0 = g * 32;
#pragma unroll
    for (int p = 0; p < 8; p++) {
        int idx = p * 128 + tid;           // 0..1023
        int bl2 = idx >> 5, hh = idx & 31;
        int b = m0 + bl2, h = h0 + hh;
        int gi = b * HH + h;
        float gate = zb[bl2 * 96 + hh]      + g_base[b * 1024 + h];
        float dyn  = zb[bl2 * 96 + 32 + hh] + g_base[b * 1024 + 512 + h];
        float tau  = softplusf(zb[bl2 * 96 + 64 + hh] + b_tau[h]);
        float hsv  = Ag[gi];
        float kd   = (sigmoidf(gate) * tanhf(dyn) - hsv) / (tau + g_leak[h] + 1e-6f);
        float dt   = x_dts[b * TT + t];
        if (stage == 0) {
            g_k1[gi]  = kd;
            g_hsA[gi] = hsv + dt * kd * (1.f / 3.f);
        } else if (stage == 1) {
            g_k2[gi]  = kd;
            g_hsB[gi] = g_h[gi] + dt * (kd - g_k1[gi] * (1.f / 3.f));
        } else if (stage == 2) {
            g_k3[gi]  = kd;
            g_hsA[gi] = g_h[gi] + dt * (g_k1[gi] - g_k2[gi] + kd);
        } else {
            g_h[gi] = g_h[gi] + dt * (g_k1[gi] + 3.f * g_k2[gi] + 3.f * g_k3[gi] + kd) * 0.125f;
        }
    }
}

// ---------------- final projection: out = h @ W_fc + b_fc -------------------
__global__ void k_final(const float* __restrict__ W_fc, const float* __restrict__ b_fc,
                        float* __restrict__ out) {
    int b = blockIdx.x, o = threadIdx.x;
    float acc = b_fc[o];
#pragma unroll 8
    for (int k = 0; k < HH; k++) acc += g_h[b * HH + k] * W_fc[k * OO + o];
    out[b * OO + o] = acc;
}

// ---------------- launch -----------------------------------------------------
extern "C" void kernel_launch(void* const* d_in, const int* in_sizes, int n_in,
                              void* d_out, int out_size) {
    const float* x_states = (const float*)d_in[0];
    const float* x_dts    = (const float*)d_in[1];
    const float* Wq    = (const float*)d_in[2];
    const float* bq    = (const float*)d_in[3];
    const float* Wk    = (const float*)d_in[4];
    const float* bk    = (const float*)d_in[5];
    const float* Wv    = (const float*)d_in[6];
    const float* bv    = (const float*)d_in[7];
    const float* W_gd  = (const float*)d_in[8];
    const float* b_gd  = (const float*)d_in[9];
    const float* W_tau = (const float*)d_in[10];
    const float* b_tau = (const float*)d_in[11];
    const float* gleak = (const float*)d_in[12];
    const float* cm    = (const float*)d_in[13];
    const float* W_fc  = (const float*)d_in[14];
    const float* b_fc  = (const float*)d_in[15];
    float* out = (float*)d_out;

    k_prep<<<512, 256>>>(cm, gleak);
    k_pack<<<3072, 256>>>(W_gd, W_tau);
    for (int t = 0; t < TT; t++) {
        if (t > 0) k_kv<<<dim3(8, 8), 256>>>(t, Wk, bk, Wv, bv);
        k_attn<<<256, 128>>>(t, x_states, Wq, bq);
        k_base<<<dim3(8, 16), 256>>>(t, x_states, W_gd, b_gd);
        for (int s = 0; s < 4; s++)
            k_stage<<<dim3(16, 8), 128>>>(t, s, b_tau, x_dts);
    }
    k_final<<<256, 32>>>(W_fc, b_fc, out);
}

// round 4
// speedup vs baseline: 1.4318x; 1.3493x over previous
#include <cuda_runtime.h>
#include <cuda_bf16.h>
#include <math.h>
#include <stdint.h>

#define BB 256
#define TT 128
#define DD 64
#define HH 512
#define AA 128
#define OO 32
#define NCAT 1536
#define NBLK 128
#define NTHR 256

// ---------------- device scratch ----------------
__device__ float g_K[BB * TT * AA];
__device__ float g_V[BB * TT * AA];
__device__ uint32_t g_WBHi[NCAT * 256];   // W^T packed bf16x2 pairs along k: [n][kq]
__device__ uint32_t g_WBLo[NCAT * 256];
__device__ float g_base[BB * 1024];
__device__ float g_ctx[BB * AA];
__device__ float g_h[BB * HH];
__device__ float g_hsA[BB * HH];
__device__ float g_hsB[BB * HH];
__device__ float g_k1[BB * HH];
__device__ float g_k2[BB * HH];
__device__ float g_k3[BB * HH];
__device__ float g_leak[HH];
__device__ unsigned g_barCnt = 0;
__device__ volatile unsigned g_barGen = 0;

__device__ __forceinline__ float softplusf(float x) {
    return (x > 20.f) ? x : log1pf(expf(x));
}
__device__ __forceinline__ float sigmoidf(float x) {
    return 1.f / (1.f + expf(-x));
}
__device__ __forceinline__ void mma16(float* d, const uint32_t* a, const uint32_t* b) {
    asm volatile(
        "mma.sync.aligned.m16n8k16.row.col.f32.bf16.bf16.f32 "
        "{%0,%1,%2,%3},{%4,%5,%6,%7},{%8,%9},{%0,%1,%2,%3};"
        : "+f"(d[0]), "+f"(d[1]), "+f"(d[2]), "+f"(d[3])
        : "r"(a[0]), "r"(a[1]), "r"(a[2]), "r"(a[3]), "r"(b[0]), "r"(b[1]));
}
__device__ __forceinline__ uint32_t pack_bf2(float a, float b) {
    __nv_bfloat162 t = __floats2bfloat162_rn(a, b);
    return *(uint32_t*)&t;
}

// ---------------- grid barrier (all 128 blocks resident) ----------------
__device__ __forceinline__ void gbar() {
    __syncthreads();
    if (threadIdx.x == 0) {
        unsigned gen = g_barGen;
        __threadfence();
        if (atomicAdd(&g_barCnt, 1u) == NBLK - 1) {
            g_barCnt = 0;
            __threadfence();
            g_barGen = gen + 1;
        } else {
            while (g_barGen == gen) { __nanosleep(32); }
        }
        __threadfence();
    }
    __syncthreads();
}

// ---------------- shared memory union ----------------
union SMem {
    struct {                       // stage GEMM
        uint32_t AsHi[32][17];
        uint32_t AsLo[32][17];
        uint32_t BsHi[96][17];     // [n][kq]; BsHi+BsLo region reused as z spill
        uint32_t BsLo[96][17];
    } st;
    struct {
        float As[192][18];
        float Ws[32][132];
    } base;
    struct {
        float Ah[32][33];
    } kv;
    struct {
        float q[2][128];
        float sc[2][128];
        float red[2][4];
    } at;
};

// ---------------- the megakernel ----------------
__global__ void __launch_bounds__(NTHR, 1) mega(
    const float* __restrict__ x_states, const float* __restrict__ x_dts,
    const float* __restrict__ Wq, const float* __restrict__ bq,
    const float* __restrict__ Wk, const float* __restrict__ bk,
    const float* __restrict__ Wv, const float* __restrict__ bv,
    const float* __restrict__ W_gd, const float* __restrict__ b_gd,
    const float* __restrict__ W_tau, const float* __restrict__ b_tau,
    const float* __restrict__ gleak, const float* __restrict__ cm,
    const float* __restrict__ W_fc, const float* __restrict__ b_fc,
    float* __restrict__ out)
{
    __shared__ SMem sm;
    int bid = blockIdx.x;
    int tid = threadIdx.x;
    int gtid = bid * NTHR + tid;
    int lane = tid & 31;
    int wid = tid >> 5;

    // ===== prep: leak, zero h, pack W^T bf16 hi/lo =====
    if (gtid < HH) g_leak[gtid] = softplusf(cm[gtid]) + softplusf(gleak[gtid]);
#pragma unroll
    for (int i = 0; i < 4; i++) g_h[i * 32768 + gtid] = 0.f;
    for (int idx = gtid; idx < NCAT * 256; idx += NBLK * NTHR) {
        int n = idx >> 8, kq = idx & 255;
        int g = n / 96, c = n - g * 96;
        int k0 = kq * 2;
        float w0, w1;
        if (c < 32) {
            w0 = W_gd[(64 + k0) * 1024 + g * 32 + c];
            w1 = W_gd[(64 + k0 + 1) * 1024 + g * 32 + c];
        } else if (c < 64) {
            w0 = W_gd[(64 + k0) * 1024 + 512 + g * 32 + (c - 32)];
            w1 = W_gd[(64 + k0 + 1) * 1024 + 512 + g * 32 + (c - 32)];
        } else {
            w0 = W_tau[k0 * 512 + g * 32 + (c - 64)];
            w1 = W_tau[(k0 + 1) * 512 + g * 32 + (c - 64)];
        }
        float h0 = __bfloat162float(__float2bfloat16(w0));
        float h1 = __bfloat162float(__float2bfloat16(w1));
        g_WBHi[idx] = pack_bf2(h0, h1);
        g_WBLo[idx] = pack_bf2(w0 - h0, w1 - h1);
    }
    gbar();

    // ===== time loop =====
    for (int t = 0; t < TT; t++) {
        // ---- phase KV: K/V row t-1 from g_h. 128 blocks: 8 mt x 16 nt ----
        if (t > 0) {
            int mt = bid >> 4, nt = bid & 15;
            int b0 = mt * 32;
            const float* W   = (nt < 8) ? Wk : Wv;
            const float* bia = (nt < 8) ? bk : bv;
            float* dst       = (nt < 8) ? g_K : g_V;
            int tx = tid & 15, ty = tid >> 4;       // ty 0..15
            int ncol = (nt & 7) * 16 + tx;
            float a0 = 0.f, a1 = 0.f;
            int lm = tid >> 3, lk = (tid & 7) * 4;
            for (int kk = 0; kk < HH; kk += 32) {
                float4 v = *(const float4*)&g_h[(b0 + lm) * HH + kk + lk];
                sm.kv.Ah[lk + 0][lm] = v.x;
                sm.kv.Ah[lk + 1][lm] = v.y;
                sm.kv.Ah[lk + 2][lm] = v.z;
                sm.kv.Ah[lk + 3][lm] = v.w;
                __syncthreads();
#pragma unroll 8
                for (int k = 0; k < 32; k++) {
                    float w = W[(kk + k) * AA + ncol];
                    a0 += sm.kv.Ah[k][ty * 2] * w;
                    a1 += sm.kv.Ah[k][ty * 2 + 1] * w;
                }
                __syncthreads();
            }
            int row = t - 1;
            dst[((b0 + ty * 2 + 0) * TT + row) * AA + ncol] = a0 + bia[ncol];
            dst[((b0 + ty * 2 + 1) * TT + row) * AA + ncol] = a1 + bia[ncol];
            gbar();
        }

        // ---- phase ATTN: 2 batches per block ----
        {
            int hB = tid >> 7;
            int lt = tid & 127;
            int b = bid * 2 + hB;
            if (t == 0) {
                g_ctx[b * AA + lt] = 0.f;
            } else {
                if (lt < DD) sm.at.sc[hB][lt] = x_states[(b * TT + t) * DD + lt];
                __syncthreads();
                float acc = bq[lt];
#pragma unroll 16
                for (int d = 0; d < DD; d++) acc += sm.at.sc[hB][d] * Wq[d * AA + lt];
                sm.at.q[hB][lt] = acc;
                __syncthreads();
                float s = -1e30f;
                if (lt < t) {
                    const float4* Kp = (const float4*)&g_K[(b * TT + lt) * AA];
                    float dot = 0.f;
#pragma unroll 8
                    for (int a4 = 0; a4 < AA / 4; a4++) {
                        float4 kv = Kp[a4];
                        dot += kv.x * sm.at.q[hB][4 * a4] + kv.y * sm.at.q[hB][4 * a4 + 1] +
                               kv.z * sm.at.q[hB][4 * a4 + 2] + kv.w * sm.at.q[hB][4 * a4 + 3];
                    }
                    s = dot * (1.f / 11.313708498984761f);
                }
                float m = s;
#pragma unroll
                for (int o = 16; o > 0; o >>= 1) m = fmaxf(m, __shfl_xor_sync(0xffffffffu, m, o));
                if ((lt & 31) == 0) sm.at.red[hB][lt >> 5] = m;
                __syncthreads();
                m = fmaxf(fmaxf(sm.at.red[hB][0], sm.at.red[hB][1]),
                          fmaxf(sm.at.red[hB][2], sm.at.red[hB][3]));
                float e = (lt < t) ? expf(s - m) : 0.f;
                float su = e;
#pragma unroll
                for (int o = 16; o > 0; o >>= 1) su += __shfl_xor_sync(0xffffffffu, su, o);
                __syncthreads();
                if ((lt & 31) == 0) sm.at.red[hB][lt >> 5] = su;
                __syncthreads();
                su = sm.at.red[hB][0] + sm.at.red[hB][1] + sm.at.red[hB][2] + sm.at.red[hB][3];
                sm.at.sc[hB][lt] = e / su;
                __syncthreads();
                float c = 0.f;
                for (int sx = 0; sx < t; sx++)
                    c += sm.at.sc[hB][sx] * g_V[(b * TT + sx) * AA + lt];
                g_ctx[b * AA + lt] = c;
            }
            gbar();
        }

        // ---- phase BASE: b_gd + x@Wx + ctx@Wc. 128 blocks: 8 jt x 16 mt ----
        {
            int jt = bid & 7, mt = bid >> 3;
            int b0 = mt * 16;
            int j0 = jt * 128;
#pragma unroll
            for (int i = 0; i < 12; i++) {
                int idx = i * 256 + tid;
                int bl = idx / 192, k = idx - bl * 192;
                float v = (k < 64) ? x_states[((b0 + bl) * TT + t) * DD + k]
                                   : g_ctx[(b0 + bl) * AA + (k - 64)];
                sm.base.As[k][bl] = v;
            }
            int tx = tid & 31;
            int ty = tid >> 5;
            float acc[2][4];
#pragma unroll
            for (int i = 0; i < 2; i++)
#pragma unroll
                for (int jx = 0; jx < 4; jx++) acc[i][jx] = 0.f;
            int wrow = tid >> 3;
            int wc0 = (tid & 7) * 4;
            for (int kc = 0; kc < 6; kc++) {
                int kbase = kc * 32;
                __syncthreads();
#pragma unroll
                for (int p = 0; p < 4; p++) {
                    int col = wc0 + p * 32;
                    int krow = kbase + wrow;
                    int wr = (krow < 64) ? krow : krow + 512;
                    *(float4*)&sm.base.Ws[wrow][col] = *(const float4*)&W_gd[wr * 1024 + j0 + col];
                }
                __syncthreads();
#pragma unroll 8
                for (int k = 0; k < 32; k++) {
                    float a0 = sm.base.As[kbase + k][ty * 2];
                    float a1 = sm.base.As[kbase + k][ty * 2 + 1];
                    float4 w = *(const float4*)&sm.base.Ws[k][tx * 4];
                    acc[0][0] += a0 * w.x; acc[0][1] += a0 * w.y;
                    acc[0][2] += a0 * w.z; acc[0][3] += a0 * w.w;
                    acc[1][0] += a1 * w.x; acc[1][1] += a1 * w.y;
                    acc[1][2] += a1 * w.z; acc[1][3] += a1 * w.w;
                }
            }
#pragma unroll
            for (int i = 0; i < 2; i++) {
                int b = b0 + ty * 2 + i;
#pragma unroll
                for (int jx = 0; jx < 4; jx++) {
                    int j = j0 + tx * 4 + jx;
                    g_base[b * 1024 + j] = acc[i][jx] + b_gd[j];
                }
            }
            gbar();
        }

        // ---- phase STAGE x4: bf16x3 split mma, fused RK epilogue ----
        for (int stage = 0; stage < 4; stage++) {
            int g = bid & 15, mt = bid >> 4;
            int m0 = mt * 32;
            const float* Ag = (stage == 0) ? g_h : ((stage == 2) ? g_hsB : g_hsA);
            int wm = (wid >> 2) * 16;     // 0 or 16
            int wn = (wid & 3) * 24;      // 0,24,48,72
            float acc[3][4];
#pragma unroll
            for (int s = 0; s < 3; s++)
#pragma unroll
                for (int i = 0; i < 4; i++) acc[s][i] = 0.f;
            int lm = tid >> 3, lk = (tid & 7) * 4;
            int r = wm + (lane >> 2);
            int qa = lane & 3;
            for (int kk = 0; kk < HH; kk += 32) {
                // stage A hi/lo (32m x 32k as bf16x2 pairs)
                float4 v = *(const float4*)&Ag[(m0 + lm) * HH + kk + lk];
                float hx = __bfloat162float(__float2bfloat16(v.x));
                float hy = __bfloat162float(__float2bfloat16(v.y));
                float hz = __bfloat162float(__float2bfloat16(v.z));
                float hw = __bfloat162float(__float2bfloat16(v.w));
                sm.st.AsHi[lm][(lk >> 1) + 0] = pack_bf2(hx, hy);
                sm.st.AsHi[lm][(lk >> 1) + 1] = pack_bf2(hz, hw);
                sm.st.AsLo[lm][(lk >> 1) + 0] = pack_bf2(v.x - hx, v.y - hy);
                sm.st.AsLo[lm][(lk >> 1) + 1] = pack_bf2(v.z - hz, v.w - hw);
                // stage B hi/lo (96n x 32k)
#pragma unroll
                for (int i = 0; i < 6; i++) {
                    int idx = i * 256 + tid;
                    int n = idx >> 4, kq = idx & 15;
                    sm.st.BsHi[n][kq] = g_WBHi[(g * 96 + n) * 256 + (kk >> 1) + kq];
                    sm.st.BsLo[n][kq] = g_WBLo[(g * 96 + n) * 256 + (kk >> 1) + kq];
                }
                __syncthreads();
#pragma unroll
                for (int kb2 = 0; kb2 < 16; kb2 += 8) {
                    uint32_t ahi[4], alo[4];
                    ahi[0] = sm.st.AsHi[r][kb2 + qa];
                    ahi[1] = sm.st.AsHi[r + 8][kb2 + qa];
                    ahi[2] = sm.st.AsHi[r][kb2 + 4 + qa];
                    ahi[3] = sm.st.AsHi[r + 8][kb2 + 4 + qa];
                    alo[0] = sm.st.AsLo[r][kb2 + qa];
                    alo[1] = sm.st.AsLo[r + 8][kb2 + qa];
                    alo[2] = sm.st.AsLo[r][kb2 + 4 + qa];
                    alo[3] = sm.st.AsLo[r + 8][kb2 + 4 + qa];
#pragma unroll
                    for (int s = 0; s < 3; s++) {
                        int n = wn + s * 8 + (lane >> 2);
                        uint32_t bhi[2], blo[2];
                        bhi[0] = sm.st.BsHi[n][kb2 + qa];
                        bhi[1] = sm.st.BsHi[n][kb2 + 4 + qa];
                        blo[0] = sm.st.BsLo[n][kb2 + qa];
                        blo[1] = sm.st.BsLo[n][kb2 + 4 + qa];
                        mma16(acc[s], ahi, bhi);
                        mma16(acc[s], alo, bhi);
                        mma16(acc[s], ahi, blo);
                    }
                }
                __syncthreads();
            }
            // spill z tile (32x96) into smem region (alias BsHi/BsLo)
            float* zb = (float*)&sm.st.BsHi[0][0];
            {
                int rr = wm + (lane >> 2);
                int cc = wn + (lane & 3) * 2;
#pragma unroll
                for (int s = 0; s < 3; s++) {
                    zb[rr * 96 + cc + s * 8]           = acc[s][0];
                    zb[rr * 96 + cc + s * 8 + 1]       = acc[s][1];
                    zb[(rr + 8) * 96 + cc + s * 8]     = acc[s][2];
                    zb[(rr + 8) * 96 + cc + s * 8 + 1] = acc[s][3];
                }
            }
            __syncthreads();
            int h0 = g * 32;
#pragma unroll
            for (int p = 0; p < 4; p++) {
                int idx = p * 256 + tid;
                int bl2 = idx >> 5, hh = idx & 31;
                int b = m0 + bl2, h = h0 + hh;
                int gi = b * HH + h;
                float gate = zb[bl2 * 96 + hh]      + g_base[b * 1024 + h];
                float dyn  = zb[bl2 * 96 + 32 + hh] + g_base[b * 1024 + 512 + h];
                float tau  = softplusf(zb[bl2 * 96 + 64 + hh] + b_tau[h]);
                float hsv  = Ag[gi];
                float kd   = (sigmoidf(gate) * tanhf(dyn) - hsv) / (tau + g_leak[h] + 1e-6f);
                float dt   = x_dts[b * TT + t];
                if (stage == 0) {
                    g_k1[gi]  = kd;
                    g_hsA[gi] = hsv + dt * kd * (1.f / 3.f);
                } else if (stage == 1) {
                    g_k2[gi]  = kd;
                    g_hsB[gi] = g_h[gi] + dt * (kd - g_k1[gi] * (1.f / 3.f));
                } else if (stage == 2) {
                    g_k3[gi]  = kd;
                    g_hsA[gi] = g_h[gi] + dt * (g_k1[gi] - g_k2[gi] + kd);
                } else {
                    g_h[gi] = g_h[gi] + dt * (g_k1[gi] + 3.f * g_k2[gi] + 3.f * g_k3[gi] + kd) * 0.125f;
                }
            }
            gbar();
        }
    }

    // ===== final projection: out = h @ W_fc + b_fc =====
    {
        int b = bid * 2 + (tid >> 7);
        int lt = tid & 127;
        if (lt < OO) {
            float acc = b_fc[lt];
#pragma unroll 8
            for (int k = 0; k < HH; k++) acc += g_h[b * HH + k] * W_fc[k * OO + lt];
            out[b * OO + lt] = acc;
        }
    }
}

// ---------------- launch ----------------
extern "C" void kernel_launch(void* const* d_in, const int* in_sizes, int n_in,
                              void* d_out, int out_size) {
    const float* x_states = (const float*)d_in[0];
    const float* x_dts    = (const float*)d_in[1];
    const float* Wq    = (const float*)d_in[2];
    const float* bq    = (const float*)d_in[3];
    const float* Wk    = (const float*)d_in[4];
    const float* bk    = (const float*)d_in[5];
    const float* Wv    = (const float*)d_in[6];
    const float* bv    = (const float*)d_in[7];
    const float* W_gd  = (const float*)d_in[8];
    const float* b_gd  = (const float*)d_in[9];
    const float* W_tau = (const float*)d_in[10];
    const float* b_tau = (const float*)d_in[11];
    const float* gleak = (const float*)d_in[12];
    const float* cm    = (const float*)d_in[13];
    const float* W_fc  = (const float*)d_in[14];
    const float* b_fc  = (const float*)d_in[15];
    float* out = (float*)d_out;

    mega<<<NBLK, NTHR>>>(x_states, x_dts, Wq, bq, Wk, bk, Wv, bv,
                         W_gd, b_gd, W_tau, b_tau, gleak, cm, W_fc, b_fc, out);
}

// round 5
// speedup vs baseline: 1.5782x; 1.1023x over previous
#include <cuda_runtime.h>
#include <cuda_bf16.h>
#include <math.h>
#include <stdint.h>

#define BB 256
#define TT 128
#define DD 64
#define HH 512
#define AA 128
#define OO 32
#define NCAT 1536
#define NBLK 128
#define NTHR 512

// ---------------- device scratch ----------------
__device__ float g_K[BB * TT * AA];
__device__ float g_V[BB * TT * AA];
__device__ uint32_t g_WBHi[NCAT * 256];   // W^T bf16x2 pairs along k: [n][kpair]
__device__ uint32_t g_WBLo[NCAT * 256];
__device__ float g_base[BB * 1024];
__device__ float g_ctx[BB * AA];
__device__ float g_h[BB * HH];
__device__ float g_hsA[BB * HH];
__device__ float g_hsB[BB * HH];
__device__ float g_k1[BB * HH];
__device__ float g_k2[BB * HH];
__device__ float g_k3[BB * HH];
__device__ float g_leak[HH];
__device__ unsigned g_cnt[9];            // 8 group barriers + 1 global
__device__ volatile unsigned g_gen[9];

__device__ __forceinline__ float softplusf(float x) {
    return (x > 20.f) ? x : log1pf(expf(x));
}
__device__ __forceinline__ float sigmoidf(float x) {
    return 1.f / (1.f + expf(-x));
}
__device__ __forceinline__ void mma16(float* d, const uint32_t* a, const uint32_t* b) {
    asm volatile(
        "mma.sync.aligned.m16n8k16.row.col.f32.bf16.bf16.f32 "
        "{%0,%1,%2,%3},{%4,%5,%6,%7},{%8,%9},{%0,%1,%2,%3};"
        : "+f"(d[0]), "+f"(d[1]), "+f"(d[2]), "+f"(d[3])
        : "r"(a[0]), "r"(a[1]), "r"(a[2]), "r"(a[3]), "r"(b[0]), "r"(b[1]));
}
__device__ __forceinline__ uint32_t pack_bf2(float a, float b) {
    __nv_bfloat162 t = __floats2bfloat162_rn(a, b);
    return *(uint32_t*)&t;
}

// ---------------- barrier (idx selects counter, nArr participants) ----------
__device__ __forceinline__ void gbar(int idx, unsigned nArr) {
    __threadfence();
    __syncthreads();
    if (threadIdx.x == 0) {
        unsigned gen = g_gen[idx];
        if (atomicAdd(&g_cnt[idx], 1u) == nArr - 1) {
            g_cnt[idx] = 0;
            __threadfence();
            g_gen[idx] = gen + 1;
        } else {
            while (g_gen[idx] == gen) __nanosleep(32);
        }
        __threadfence();
    }
    __syncthreads();
}

// ---------------- shared memory layouts (dynamic) ----------------
struct SMemSt {
    uint32_t AsHi[2][32][17];
    uint32_t AsLo[2][32][17];
    uint32_t BsHi[2][96][17];
    uint32_t BsLo[2][96][17];
    float z[2][32][96];
};
struct SMemBase {
    float As[192][36];
    float Ws[32][68];
};
struct SMemAt {
    float hrow[2][512];
    float q[2][128];
    float sc[2][128];
    float ctxp[2][2][128];
    float xs[2][64];
    float red[2][8];
};
#define SMEM_BYTES 61440

// ---------------- megakernel ----------------
__global__ void __launch_bounds__(NTHR, 1) mega(
    const float* __restrict__ x_states, const float* __restrict__ x_dts,
    const float* __restrict__ Wq, const float* __restrict__ bq,
    const float* __restrict__ Wk, const float* __restrict__ bk,
    const float* __restrict__ Wv, const float* __restrict__ bv,
    const float* __restrict__ W_gd, const float* __restrict__ b_gd,
    const float* __restrict__ W_tau, const float* __restrict__ b_tau,
    const float* __restrict__ gleak, const float* __restrict__ cm,
    const float* __restrict__ W_fc, const float* __restrict__ b_fc,
    float* __restrict__ out)
{
    extern __shared__ char smraw[];
    SMemSt&   st = *(SMemSt*)smraw;
    SMemBase& sb = *(SMemBase*)smraw;
    SMemAt&   sa = *(SMemAt*)smraw;

    int bid = blockIdx.x;
    int tid = threadIdx.x;
    int gtid = bid * NTHR + tid;
    int lane = tid & 31;
    int wid = tid >> 5;
    int gid = bid >> 4;                 // group (32 batches)

    // ===== prep: leak, zero h, pack W^T bf16 hi/lo =====
    if (gtid < HH) g_leak[gtid] = softplusf(cm[gtid]) + softplusf(gleak[gtid]);
    g_h[gtid] = 0.f;
    g_h[65536 + gtid] = 0.f;
    for (int idx = gtid; idx < NCAT * 256; idx += NBLK * NTHR) {
        int n = idx >> 8, kq = idx & 255;
        int g = n / 96, c = n - g * 96;
        int k0 = kq * 2;
        float w0, w1;
        if (c < 32) {
            w0 = W_gd[(64 + k0) * 1024 + g * 32 + c];
            w1 = W_gd[(64 + k0 + 1) * 1024 + g * 32 + c];
        } else if (c < 64) {
            w0 = W_gd[(64 + k0) * 1024 + 512 + g * 32 + (c - 32)];
            w1 = W_gd[(64 + k0 + 1) * 1024 + 512 + g * 32 + (c - 32)];
        } else {
            w0 = W_tau[k0 * 512 + g * 32 + (c - 64)];
            w1 = W_tau[(k0 + 1) * 512 + g * 32 + (c - 64)];
        }
        float h0 = __bfloat162float(__float2bfloat16(w0));
        float h1 = __bfloat162float(__float2bfloat16(w1));
        g_WBHi[idx] = pack_bf2(h0, h1);
        g_WBLo[idx] = pack_bf2(w0 - h0, w1 - h1);
    }
    gbar(8, NBLK);   // global: pack done

    // ===== time loop (groups of 16 blocks run independently) =====
    for (int t = 0; t < TT; t++) {
        // ---- ATTN (+fused KV row t-1): block owns batches 2bid, 2bid+1 ----
        {
            int hB = tid >> 8;           // batch half
            int lt = tid & 255;
            int b = bid * 2 + hB;
            if (t == 0) {
                if (lt < 128) g_ctx[b * AA + lt] = 0.f;
            } else {
                sa.hrow[hB][lt]       = g_h[b * HH + lt];
                sa.hrow[hB][256 + lt] = g_h[b * HH + 256 + lt];
                if (lt < DD) sa.xs[hB][lt] = x_states[(b * TT + t) * DD + lt];
                __syncthreads();
                // KV column
                {
                    const float* W = (lt < 128) ? Wk : Wv;
                    int c = lt & 127;
                    float acc = (lt < 128) ? bk[c] : bv[c];
                    const float* hr = sa.hrow[hB];
#pragma unroll 8
                    for (int k = 0; k < HH; k++) acc += hr[k] * W[k * AA + c];
                    float* dst = (lt < 128) ? g_K : g_V;
                    dst[(b * TT + (t - 1)) * AA + c] = acc;
                }
                // Q
                if (lt < 128) {
                    float qv = bq[lt];
#pragma unroll 16
                    for (int d = 0; d < DD; d++) qv += sa.xs[hB][d] * Wq[d * AA + lt];
                    sa.q[hB][lt] = qv;
                }
                __threadfence_block();
                __syncthreads();
                // scores (lane lt = history index)
                float s = -1e30f;
                if (lt < t) {
                    const float4* Kp = (const float4*)&g_K[(b * TT + lt) * AA];
                    const float* qh = sa.q[hB];
                    float dot = 0.f;
#pragma unroll 8
                    for (int a4 = 0; a4 < AA / 4; a4++) {
                        float4 kv = Kp[a4];
                        dot += kv.x * qh[4 * a4] + kv.y * qh[4 * a4 + 1] +
                               kv.z * qh[4 * a4 + 2] + kv.w * qh[4 * a4 + 3];
                    }
                    s = dot * (1.f / 11.313708498984761f);
                }
                float m = s;
#pragma unroll
                for (int o = 16; o > 0; o >>= 1) m = fmaxf(m, __shfl_xor_sync(0xffffffffu, m, o));
                if (lane == 0) sa.red[hB][wid & 7] = m;
                __syncthreads();
                m = sa.red[hB][0];
#pragma unroll
                for (int i = 1; i < 8; i++) m = fmaxf(m, sa.red[hB][i]);
                float e = (lt < t) ? expf(s - m) : 0.f;
                float su = e;
#pragma unroll
                for (int o = 16; o > 0; o >>= 1) su += __shfl_xor_sync(0xffffffffu, su, o);
                __syncthreads();
                if (lane == 0) sa.red[hB][wid & 7] = su;
                __syncthreads();
                su = 0.f;
#pragma unroll
                for (int i = 0; i < 8; i++) su += sa.red[hB][i];
                if (lt < 128) sa.sc[hB][lt] = e / su;
                __syncthreads();
                // ctx (split history across two thread halves)
                {
                    int a = lt & 127, th = lt >> 7;
                    float c = 0.f;
                    for (int sx = th; sx < t; sx += 2)
                        c += sa.sc[hB][sx] * g_V[(b * TT + sx) * AA + a];
                    sa.ctxp[hB][th][a] = c;
                }
                __syncthreads();
                if (lt < 128)
                    g_ctx[b * AA + lt] = sa.ctxp[hB][0][lt] + sa.ctxp[hB][1][lt];
            }
            gbar(gid, 16);
        }

        // ---- BASE: group's 16 blocks split 1024 cols; 32 batches ----
        {
            int jt = bid & 15;
            int b0 = gid * 32;
            int j0 = jt * 64;
#pragma unroll
            for (int i = 0; i < 12; i++) {
                int idx = i * 512 + tid;            // < 6144
                int bl = idx / 192, k = idx - bl * 192;
                float v = (k < 64) ? x_states[((b0 + bl) * TT + t) * DD + k]
                                   : g_ctx[(b0 + bl) * AA + (k - 64)];
                sb.As[k][bl] = v;
            }
            int j = tid & 63;
            int mg = tid >> 6;                      // 0..7 -> rows mg*4..+3
            float acc[4] = {0.f, 0.f, 0.f, 0.f};
            int wrow = tid >> 4;                    // 0..31
            int wc = (tid & 15) * 4;                // 0..60
            for (int kc = 0; kc < 6; kc++) {
                __syncthreads();
                int krow = kc * 32 + wrow;
                int wr = (krow < 64) ? krow : krow + 512;
                *(float4*)&sb.Ws[wrow][wc] = *(const float4*)&W_gd[wr * 1024 + j0 + wc];
                __syncthreads();
#pragma unroll 8
                for (int k = 0; k < 32; k++) {
                    float w = sb.Ws[k][j];
                    float4 av = *(const float4*)&sb.As[kc * 32 + k][mg * 4];
                    acc[0] += av.x * w; acc[1] += av.y * w;
                    acc[2] += av.z * w; acc[3] += av.w * w;
                }
            }
            float bg = b_gd[j0 + j];
#pragma unroll
            for (int i = 0; i < 4; i++)
                g_base[(b0 + mg * 4 + i) * 1024 + j0 + j] = acc[i] + bg;
            gbar(gid, 16);
        }

        // ---- 4 RK stages: bf16x3 split mma, k-split across warp halves ----
        for (int stage = 0; stage < 4; stage++) {
            int g = bid & 15;
            int m0 = gid * 32;
            const float* Ag = (stage == 0) ? g_h : ((stage == 2) ? g_hsB : g_hsA);
            int kh = wid >> 3;                      // k half (0: k<256, 1: k>=256)
            int wl = wid & 7;
            int wm = (wl >> 2) * 16;
            int wn = (wl & 3) * 24;
            float acc[3][4];
#pragma unroll
            for (int s = 0; s < 3; s++)
#pragma unroll
                for (int i = 0; i < 4; i++) acc[s][i] = 0.f;
            int ltid = tid & 255;
            int lm = ltid >> 3, lk = (ltid & 7) * 4;
            int r = wm + (lane >> 2);
            int qa = lane & 3;
            int kk0 = kh * 256;
            for (int it = 0; it < 8; it++) {
                int kk = kk0 + it * 32;
                float4 v = *(const float4*)&Ag[(m0 + lm) * HH + kk + lk];
                float hx = __bfloat162float(__float2bfloat16(v.x));
                float hy = __bfloat162float(__float2bfloat16(v.y));
                float hz = __bfloat162float(__float2bfloat16(v.z));
                float hw = __bfloat162float(__float2bfloat16(v.w));
                st.AsHi[kh][lm][(lk >> 1) + 0] = pack_bf2(hx, hy);
                st.AsHi[kh][lm][(lk >> 1) + 1] = pack_bf2(hz, hw);
                st.AsLo[kh][lm][(lk >> 1) + 0] = pack_bf2(v.x - hx, v.y - hy);
                st.AsLo[kh][lm][(lk >> 1) + 1] = pack_bf2(v.z - hz, v.w - hw);
#pragma unroll
                for (int i = 0; i < 6; i++) {
                    int idx = i * 256 + ltid;       // < 1536
                    int n = idx >> 4, kq = idx & 15;
                    st.BsHi[kh][n][kq] = g_WBHi[(g * 96 + n) * 256 + (kk >> 1) + kq];
                    st.BsLo[kh][n][kq] = g_WBLo[(g * 96 + n) * 256 + (kk >> 1) + kq];
                }
                __syncthreads();
#pragma unroll
                for (int kb2 = 0; kb2 < 16; kb2 += 8) {
                    uint32_t ahi[4], alo[4];
                    ahi[0] = st.AsHi[kh][r][kb2 + qa];
                    ahi[1] = st.AsHi[kh][r + 8][kb2 + qa];
                    ahi[2] = st.AsHi[kh][r][kb2 + 4 + qa];
                    ahi[3] = st.AsHi[kh][r + 8][kb2 + 4 + qa];
                    alo[0] = st.AsLo[kh][r][kb2 + qa];
                    alo[1] = st.AsLo[kh][r + 8][kb2 + qa];
                    alo[2] = st.AsLo[kh][r][kb2 + 4 + qa];
                    alo[3] = st.AsLo[kh][r + 8][kb2 + 4 + qa];
#pragma unroll
                    for (int s = 0; s < 3; s++) {
                        int n = wn + s * 8 + (lane >> 2);
                        uint32_t bhi[2], blo[2];
                        bhi[0] = st.BsHi[kh][n][kb2 + qa];
                        bhi[1] = st.BsHi[kh][n][kb2 + 4 + qa];
                        blo[0] = st.BsLo[kh][n][kb2 + qa];
                        blo[1] = st.BsLo[kh][n][kb2 + 4 + qa];
                        mma16(acc[s], ahi, bhi);
                        mma16(acc[s], alo, bhi);
                        mma16(acc[s], ahi, blo);
                    }
                }
                __syncthreads();
            }
            // spill partials
            {
                int rr = wm + (lane >> 2);
                int cc = wn + (lane & 3) * 2;
#pragma unroll
                for (int s = 0; s < 3; s++) {
                    st.z[kh][rr][cc + s * 8]         = acc[s][0];
                    st.z[kh][rr][cc + s * 8 + 1]     = acc[s][1];
                    st.z[kh][rr + 8][cc + s * 8]     = acc[s][2];
                    st.z[kh][rr + 8][cc + s * 8 + 1] = acc[s][3];
                }
            }
            __syncthreads();
            int h0 = g * 32;
#pragma unroll
            for (int p = 0; p < 2; p++) {
                int idx = p * 512 + tid;            // 0..1023
                int bl = idx >> 5, hh = idx & 31;
                int b = m0 + bl, h = h0 + hh;
                int gi = b * HH + h;
                float gate = st.z[0][bl][hh]      + st.z[1][bl][hh]      + g_base[b * 1024 + h];
                float dyn  = st.z[0][bl][32 + hh] + st.z[1][bl][32 + hh] + g_base[b * 1024 + 512 + h];
                float tau  = softplusf(st.z[0][bl][64 + hh] + st.z[1][bl][64 + hh] + b_tau[h]);
                float hsv  = Ag[gi];
                float kd   = (sigmoidf(gate) * tanhf(dyn) - hsv) / (tau + g_leak[h] + 1e-6f);
                float dt   = x_dts[b * TT + t];
                if (stage == 0) {
                    g_k1[gi]  = kd;
                    g_hsA[gi] = hsv + dt * kd * (1.f / 3.f);
                } else if (stage == 1) {
                    g_k2[gi]  = kd;
                    g_hsB[gi] = g_h[gi] + dt * (kd - g_k1[gi] * (1.f / 3.f));
                } else if (stage == 2) {
                    g_k3[gi]  = kd;
                    g_hsA[gi] = g_h[gi] + dt * (g_k1[gi] - g_k2[gi] + kd);
                } else {
                    g_h[gi] = g_h[gi] + dt * (g_k1[gi] + 3.f * g_k2[gi] + 3.f * g_k3[gi] + kd) * 0.125f;
                }
            }
            gbar(gid, 16);
        }
    }

    // ===== final projection for this block's 2 batches =====
    {
        int b = bid * 2 + (tid >> 8);
        int lt = tid & 255;
        if (lt < OO) {
            float acc = b_fc[lt];
#pragma unroll 8
            for (int k = 0; k < HH; k++) acc += g_h[b * HH + k] * W_fc[k * OO + lt];
            out[b * OO + lt] = acc;
        }
    }
}

// ---------------- launch ----------------
extern "C" void kernel_launch(void* const* d_in, const int* in_sizes, int n_in,
                              void* d_out, int out_size) {
    const float* x_states = (const float*)d_in[0];
    const float* x_dts    = (const float*)d_in[1];
    const float* Wq    = (const float*)d_in[2];
    const float* bq    = (const float*)d_in[3];
    const float* Wk    = (const float*)d_in[4];
    const float* bk    = (const float*)d_in[5];
    const float* Wv    = (const float*)d_in[6];
    const float* bv    = (const float*)d_in[7];
    const float* W_gd  = (const float*)d_in[8];
    const float* b_gd  = (const float*)d_in[9];
    const float* W_tau = (const float*)d_in[10];
    const float* b_tau = (const float*)d_in[11];
    const float* gleak = (const float*)d_in[12];
    const float* cm    = (const float*)d_in[13];
    const float* W_fc  = (const float*)d_in[14];
    const float* b_fc  = (const float*)d_in[15];
    float* out = (float*)d_out;

    cudaFuncSetAttribute(mega, cudaFuncAttributeMaxDynamicSharedMemorySize, SMEM_BYTES);
    mega<<<NBLK, NTHR, SMEM_BYTES>>>(x_states, x_dts, Wq, bq, Wk, bk, Wv, bv,
                                     W_gd, b_gd, W_tau, b_tau, gleak, cm,
                                     W_fc, b_fc, out);
}

// round 6
// speedup vs baseline: 1.7364x; 1.1003x over previous
#include <cuda_runtime.h>
#include <cuda_bf16.h>
#include <math.h>
#include <stdint.h>

#define BB 256
#define TT 128
#define DD 64
#define HH 512
#define AA 128
#define OO 32
#define NCAT 1536
#define NBLK 128
#define NTHR 512

// ---------------- device scratch ----------------
__device__ float g_K[BB * TT * AA];
__device__ float g_V[BB * TT * AA];
__device__ uint32_t g_WBHi[NCAT * 256];   // W^T bf16x2 pairs along k: [n][kpair]
__device__ uint32_t g_WBLo[NCAT * 256];
__device__ float g_ctx[BB * AA];
__device__ float g_h[BB * HH];
__device__ float g_dA[BB * HH];           // delta buffers (h_s - h)
__device__ float g_dB[BB * HH];
__device__ float g_k1[BB * HH];
__device__ float g_k2[BB * HH];
__device__ float g_k3[BB * HH];
__device__ float g_leak[HH];
__device__ unsigned g_cnt[9];
__device__ volatile unsigned g_gen[9];

__device__ __forceinline__ float softplusf(float x) {
    return (x > 20.f) ? x : log1pf(expf(x));
}
__device__ __forceinline__ float sigmoidf(float x) {
    return 1.f / (1.f + expf(-x));
}
__device__ __forceinline__ void mma16(float* d, const uint32_t* a, const uint32_t* b) {
    asm volatile(
        "mma.sync.aligned.m16n8k16.row.col.f32.bf16.bf16.f32 "
        "{%0,%1,%2,%3},{%4,%5,%6,%7},{%8,%9},{%0,%1,%2,%3};"
        : "+f"(d[0]), "+f"(d[1]), "+f"(d[2]), "+f"(d[3])
        : "r"(a[0]), "r"(a[1]), "r"(a[2]), "r"(a[3]), "r"(b[0]), "r"(b[1]));
}
__device__ __forceinline__ uint32_t pack_bf2(float a, float b) {
    __nv_bfloat162 t = __floats2bfloat162_rn(a, b);
    return *(uint32_t*)&t;
}

// ---------------- barrier ----------------
__device__ __forceinline__ void gbar(int idx, unsigned nArr) {
    __threadfence();
    __syncthreads();
    if (threadIdx.x == 0) {
        unsigned gen = g_gen[idx];
        if (atomicAdd(&g_cnt[idx], 1u) == nArr - 1) {
            g_cnt[idx] = 0;
            __threadfence();
            g_gen[idx] = gen + 1;
        } else {
            while (g_gen[idx] == gen) __nanosleep(32);
        }
        __threadfence();
    }
    __syncthreads();
}

// smem layout:
//  [0, 8192):      sbase[32][64]        (persists across step's 4 stages)
//  [8192, 20480):  sz0[32][96]          (persists across step's 4 stages)
//  [20480, ...):   union:
//    stage: AsHi[64][17]u32 | AsLo[64][17] | BsHi[192][17] | BsLo[192][17] | zz[64][96]f
//           (zz also aliased as cz[32][192] for base staging)
//    kv:    hrow[32][516]f  (66048 B)
//    attn:  small scratch
#define OFF_UN    20480
#define OFF_ASHI  (OFF_UN)
#define OFF_ASLO  (OFF_UN + 4352)
#define OFF_BSHI  (OFF_UN + 8704)
#define OFF_BSLO  (OFF_UN + 21760)
#define OFF_Z     (OFF_UN + 34816)
#define SMEM_BYTES (20480 + 66048)

typedef uint32_t U17[17];

// ---------------- megakernel ----------------
__global__ void __launch_bounds__(NTHR, 1) mega(
    const float* __restrict__ x_states, const float* __restrict__ x_dts,
    const float* __restrict__ Wq, const float* __restrict__ bq,
    const float* __restrict__ Wk, const float* __restrict__ bk,
    const float* __restrict__ Wv, const float* __restrict__ bv,
    const float* __restrict__ W_gd, const float* __restrict__ b_gd,
    const float* __restrict__ W_tau, const float* __restrict__ b_tau,
    const float* __restrict__ gleak, const float* __restrict__ cm,
    const float* __restrict__ W_fc, const float* __restrict__ b_fc,
    float* __restrict__ out)
{
    extern __shared__ char smraw[];
    float (*sbase)[64] = (float(*)[64])(smraw);
    float (*sz0)[96]   = (float(*)[96])(smraw + 8192);
    char* un = smraw + OFF_UN;

    int bid = blockIdx.x;
    int tid = threadIdx.x;
    int gtid = bid * NTHR + tid;
    int lane = tid & 31;
    int wid = tid >> 5;
    int gid = bid >> 4;                 // batch group (32 batches)
    int hg  = bid & 15;                 // h-col group (32 h)
    int m0 = gid * 32;
    int h0 = hg * 32;

    // ===== prep =====
    if (gtid < HH) g_leak[gtid] = softplusf(cm[gtid]) + softplusf(gleak[gtid]);
    g_h[gtid] = 0.f;
    g_h[65536 + gtid] = 0.f;
    for (int idx = gtid; idx < NCAT * 256; idx += NBLK * NTHR) {
        int n = idx >> 8, kq = idx & 255;
        int g = n / 96, c = n - g * 96;
        int k0 = kq * 2;
        float w0, w1;
        if (c < 32) {
            w0 = W_gd[(64 + k0) * 1024 + g * 32 + c];
            w1 = W_gd[(64 + k0 + 1) * 1024 + g * 32 + c];
        } else if (c < 64) {
            w0 = W_gd[(64 + k0) * 1024 + 512 + g * 32 + (c - 32)];
            w1 = W_gd[(64 + k0 + 1) * 1024 + 512 + g * 32 + (c - 32)];
        } else {
            w0 = W_tau[k0 * 512 + g * 32 + (c - 64)];
            w1 = W_tau[(k0 + 1) * 512 + g * 32 + (c - 64)];
        }
        float hi0 = __bfloat162float(__float2bfloat16(w0));
        float hi1 = __bfloat162float(__float2bfloat16(w1));
        g_WBHi[idx] = pack_bf2(hi0, hi1);
        g_WBLo[idx] = pack_bf2(w0 - hi0, w1 - hi1);
    }
    gbar(8, NBLK);

    // ===== time loop =====
    for (int t = 0; t < TT; t++) {
        // ---- KV: row t-1 = g_h @ [Wk|Wv]; tile 32b x 16n per block ----
        if (t > 0) {
            float (*hrow)[516] = (float(*)[516])un;
#pragma unroll
            for (int i = 0; i < 8; i++) {
                int idx = i * 512 + tid;            // < 4096 float4
                int rr = idx >> 7, c4 = (idx & 127) << 2;
                float4 v = *(const float4*)&g_h[(m0 + rr) * HH + c4];
                *(float4*)&hrow[rr][c4] = v;
            }
            __syncthreads();
            int tx = tid & 15, ty = tid >> 4;       // ty 0..31 = batch
            int nn = hg * 16 + tx;                   // 0..255
            const float* W = (nn < 128) ? Wk : Wv;
            int ncol = nn & 127;
            float acc = (nn < 128) ? bk[ncol] : bv[ncol];
            const float* hr = hrow[ty];
#pragma unroll 8
            for (int k = 0; k < HH; k++) acc += hr[k] * W[k * AA + ncol];
            float* dst = (nn < 128) ? g_K : g_V;
            dst[((m0 + ty) * TT + (t - 1)) * AA + ncol] = acc;
            gbar(gid, 16);
        }

        // ---- ATTN: 2 batches per block ----
        {
            float* aq   = (float*)un;               // [2][128]
            float* asc  = aq + 256;                 // [2][128]
            float* actx = asc + 256;                // [2][2][128]
            float* axs  = actx + 512;               // [2][64]
            float* ared = axs + 128;                // [2][8]
            int hB = tid >> 8;
            int lt = tid & 255;
            int b = bid * 2 + hB;
            if (t == 0) {
                if (lt < 128) g_ctx[b * AA + lt] = 0.f;
            } else {
                if (lt < DD) axs[hB * 64 + lt] = x_states[(b * TT + t) * DD + lt];
                __syncthreads();
                if (lt < 128) {
                    float qv = bq[lt];
#pragma unroll 16
                    for (int d = 0; d < DD; d++) qv += axs[hB * 64 + d] * Wq[d * AA + lt];
                    aq[hB * 128 + lt] = qv;
                }
                __syncthreads();
                float s = -1e30f;
                if (lt < t) {
                    const float4* Kp = (const float4*)&g_K[(b * TT + lt) * AA];
                    const float* qh = &aq[hB * 128];
                    float dot = 0.f;
#pragma unroll 8
                    for (int a4 = 0; a4 < AA / 4; a4++) {
                        float4 kv = Kp[a4];
                        dot += kv.x * qh[4 * a4] + kv.y * qh[4 * a4 + 1] +
                               kv.z * qh[4 * a4 + 2] + kv.w * qh[4 * a4 + 3];
                    }
                    s = dot * (1.f / 11.313708498984761f);
                }
                float m = s;
#pragma unroll
                for (int o = 16; o > 0; o >>= 1) m = fmaxf(m, __shfl_xor_sync(0xffffffffu, m, o));
                if (lane == 0) ared[hB * 8 + (wid & 7)] = m;
                __syncthreads();
                m = ared[hB * 8];
#pragma unroll
                for (int i = 1; i < 8; i++) m = fmaxf(m, ared[hB * 8 + i]);
                float e = (lt < t) ? expf(s - m) : 0.f;
                float su = e;
#pragma unroll
                for (int o = 16; o > 0; o >>= 1) su += __shfl_xor_sync(0xffffffffu, su, o);
                __syncthreads();
                if (lane == 0) ared[hB * 8 + (wid & 7)] = su;
                __syncthreads();
                su = 0.f;
#pragma unroll
                for (int i = 0; i < 8; i++) su += ared[hB * 8 + i];
                if (lt < 128) asc[hB * 128 + lt] = e / su;
                __syncthreads();
                {
                    int a = lt & 127, th = lt >> 7;
                    float c = 0.f;
                    for (int sx = th; sx < t; sx += 2)
                        c += asc[hB * 128 + sx] * g_V[(b * TT + sx) * AA + a];
                    actx[(hB * 2 + th) * 128 + a] = c;
                }
                __syncthreads();
                if (lt < 128)
                    g_ctx[b * AA + lt] = actx[hB * 256 + lt] + actx[hB * 256 + 128 + lt];
            }
            gbar(gid, 16);
        }

        // ---- 4 RK stages ----
        U17* AsHi = (U17*)(smraw + OFF_ASHI);       // [64] = kh*32 + m
        U17* AsLo = (U17*)(smraw + OFF_ASLO);
        U17* BsHi = (U17*)(smraw + OFF_BSHI);       // [192] = kh*96 + n
        U17* BsLo = (U17*)(smraw + OFF_BSLO);
        float (*zz)[96] = (float(*)[96])(smraw + OFF_Z);   // [64] = kh*32 + m

        for (int stage = 0; stage < 4; stage++) {
            const float* Ag = (stage == 0) ? g_h : ((stage == 2) ? g_dB : g_dA);
            int kh = wid >> 3;
            int wl = wid & 7;
            int wm = (wl >> 2) * 16;
            int wn = (wl & 3) * 24;
            int ltid = tid & 255;
            int lm = ltid >> 3, lk = (ltid & 7) * 4;
            int r = wm + (lane >> 2);
            int qa = lane & 3;
            int kk0 = kh * 256;

            if (stage == 0) {
                // base GEMM into sbase (staging in cz = zz region)
                float (*cz)[192] = (float(*)[192])(smraw + OFF_Z);
#pragma unroll
                for (int i = 0; i < 12; i++) {
                    int idx = i * 512 + tid;        // < 6144
                    int bl = idx / 192, k = idx - bl * 192;
                    cz[bl][k] = (k < 64) ? x_states[((m0 + bl) * TT + t) * DD + k]
                                         : g_ctx[(m0 + bl) * AA + (k - 64)];
                }
                __syncthreads();
                {
                    int tx2 = tid & 63, ty2 = tid >> 6;
                    int col = (tx2 < 32) ? (h0 + tx2) : (512 + h0 + (tx2 - 32));
                    float acc[4] = {0.f, 0.f, 0.f, 0.f};
#pragma unroll 8
                    for (int k = 0; k < 64; k++) {
                        float w = W_gd[k * 1024 + col];
                        acc[0] += cz[ty2 * 4 + 0][k] * w;
                        acc[1] += cz[ty2 * 4 + 1][k] * w;
                        acc[2] += cz[ty2 * 4 + 2][k] * w;
                        acc[3] += cz[ty2 * 4 + 3][k] * w;
                    }
#pragma unroll 8
                    for (int k = 64; k < 192; k++) {
                        float w = W_gd[(k + 512) * 1024 + col];
                        acc[0] += cz[ty2 * 4 + 0][k] * w;
                        acc[1] += cz[ty2 * 4 + 1][k] * w;
                        acc[2] += cz[ty2 * 4 + 2][k] * w;
                        acc[3] += cz[ty2 * 4 + 3][k] * w;
                    }
                    float bg = b_gd[col];
#pragma unroll
                    for (int i2 = 0; i2 < 4; i2++)
                        sbase[ty2 * 4 + i2][tx2] = acc[i2] + bg;
                }
                __syncthreads();

                // 3-term bf16 split GEMM: z0 = h @ Wpack
                float acc[3][4];
#pragma unroll
                for (int s = 0; s < 3; s++)
#pragma unroll
                    for (int i = 0; i < 4; i++) acc[s][i] = 0.f;
                for (int it = 0; it < 8; it++) {
                    int kk = kk0 + it * 32;
                    float4 v = *(const float4*)&Ag[(m0 + lm) * HH + kk + lk];
                    float hx = __bfloat162float(__float2bfloat16(v.x));
                    float hy = __bfloat162float(__float2bfloat16(v.y));
                    float hz = __bfloat162float(__float2bfloat16(v.z));
                    float hw = __bfloat162float(__float2bfloat16(v.w));
                    AsHi[kh * 32 + lm][(lk >> 1) + 0] = pack_bf2(hx, hy);
                    AsHi[kh * 32 + lm][(lk >> 1) + 1] = pack_bf2(hz, hw);
                    AsLo[kh * 32 + lm][(lk >> 1) + 0] = pack_bf2(v.x - hx, v.y - hy);
                    AsLo[kh * 32 + lm][(lk >> 1) + 1] = pack_bf2(v.z - hz, v.w - hw);
#pragma unroll
                    for (int i = 0; i < 6; i++) {
                        int idx = i * 256 + ltid;
                        int n = idx >> 4, kq = idx & 15;
                        BsHi[kh * 96 + n][kq] = g_WBHi[(hg * 96 + n) * 256 + (kk >> 1) + kq];
                        BsLo[kh * 96 + n][kq] = g_WBLo[(hg * 96 + n) * 256 + (kk >> 1) + kq];
                    }
                    __syncthreads();
#pragma unroll
                    for (int kb2 = 0; kb2 < 16; kb2 += 8) {
                        uint32_t ahi[4], alo[4];
                        ahi[0] = AsHi[kh * 32 + r][kb2 + qa];
                        ahi[1] = AsHi[kh * 32 + r + 8][kb2 + qa];
                        ahi[2] = AsHi[kh * 32 + r][kb2 + 4 + qa];
                        ahi[3] = AsHi[kh * 32 + r + 8][kb2 + 4 + qa];
                        alo[0] = AsLo[kh * 32 + r][kb2 + qa];
                        alo[1] = AsLo[kh * 32 + r + 8][kb2 + qa];
                        alo[2] = AsLo[kh * 32 + r][kb2 + 4 + qa];
                        alo[3] = AsLo[kh * 32 + r + 8][kb2 + 4 + qa];
#pragma unroll
                        for (int s = 0; s < 3; s++) {
                            int n = wn + s * 8 + (lane >> 2);
                            uint32_t bhi[2], blo[2];
                            bhi[0] = BsHi[kh * 96 + n][kb2 + qa];
                            bhi[1] = BsHi[kh * 96 + n][kb2 + 4 + qa];
                            blo[0] = BsLo[kh * 96 + n][kb2 + qa];
                            blo[1] = BsLo[kh * 96 + n][kb2 + 4 + qa];
                            mma16(acc[s], ahi, bhi);
                            mma16(acc[s], alo, bhi);
                            mma16(acc[s], ahi, blo);
                        }
                    }
                    __syncthreads();
                }
                // spill & combine into sz0
                {
                    int rr = wm + (lane >> 2);
                    int cc = wn + (lane & 3) * 2;
#pragma unroll
                    for (int s = 0; s < 3; s++) {
                        zz[kh * 32 + rr][cc + s * 8]         = acc[s][0];
                        zz[kh * 32 + rr][cc + s * 8 + 1]     = acc[s][1];
                        zz[kh * 32 + rr + 8][cc + s * 8]     = acc[s][2];
                        zz[kh * 32 + rr + 8][cc + s * 8 + 1] = acc[s][3];
                    }
                }
                __syncthreads();
#pragma unroll
                for (int i = 0; i < 6; i++) {
                    int idx = i * 512 + tid;        // < 3072
                    int bl = idx / 96, c = idx - bl * 96;
                    sz0[bl][c] = zz[bl][c] + zz[32 + bl][c];
                }
                __syncthreads();
            } else {
                // 1-term bf16 GEMM on small delta: zd = delta @ Wpack_hi
                float acc[3][4];
#pragma unroll
                for (int s = 0; s < 3; s++)
#pragma unroll
                    for (int i = 0; i < 4; i++) acc[s][i] = 0.f;
                for (int it = 0; it < 8; it++) {
                    int kk = kk0 + it * 32;
                    float4 v = *(const float4*)&Ag[(m0 + lm) * HH + kk + lk];
                    AsHi[kh * 32 + lm][(lk >> 1) + 0] = pack_bf2(v.x, v.y);
                    AsHi[kh * 32 + lm][(lk >> 1) + 1] = pack_bf2(v.z, v.w);
#pragma unroll
                    for (int i = 0; i < 6; i++) {
                        int idx = i * 256 + ltid;
                        int n = idx >> 4, kq = idx & 15;
                        BsHi[kh * 96 + n][kq] = g_WBHi[(hg * 96 + n) * 256 + (kk >> 1) + kq];
                    }
                    __syncthreads();
#pragma unroll
                    for (int kb2 = 0; kb2 < 16; kb2 += 8) {
                        uint32_t ahi[4];
                        ahi[0] = AsHi[kh * 32 + r][kb2 + qa];
                        ahi[1] = AsHi[kh * 32 + r + 8][kb2 + qa];
                        ahi[2] = AsHi[kh * 32 + r][kb2 + 4 + qa];
                        ahi[3] = AsHi[kh * 32 + r + 8][kb2 + 4 + qa];
#pragma unroll
                        for (int s = 0; s < 3; s++) {
                            int n = wn + s * 8 + (lane >> 2);
                            uint32_t bhi[2];
                            bhi[0] = BsHi[kh * 96 + n][kb2 + qa];
                            bhi[1] = BsHi[kh * 96 + n][kb2 + 4 + qa];
                            mma16(acc[s], ahi, bhi);
                        }
                    }
                    __syncthreads();
                }
                {
                    int rr = wm + (lane >> 2);
                    int cc = wn + (lane & 3) * 2;
#pragma unroll
                    for (int s = 0; s < 3; s++) {
                        zz[kh * 32 + rr][cc + s * 8]         = acc[s][0];
                        zz[kh * 32 + rr][cc + s * 8 + 1]     = acc[s][1];
                        zz[kh * 32 + rr + 8][cc + s * 8]     = acc[s][2];
                        zz[kh * 32 + rr + 8][cc + s * 8 + 1] = acc[s][3];
                    }
                }
                __syncthreads();
            }

            // ---- fused RK epilogue (32b x 32h slice) ----
#pragma unroll
            for (int p = 0; p < 2; p++) {
                int idx = p * 512 + tid;            // 0..1023
                int bl = idx >> 5, hh = idx & 31;
                int b = m0 + bl, h = h0 + hh;
                int gi = b * HH + h;
                float zg, zd, zt;
                if (stage == 0) {
                    zg = sz0[bl][hh];
                    zd = sz0[bl][32 + hh];
                    zt = sz0[bl][64 + hh];
                } else {
                    zg = sz0[bl][hh]      + zz[bl][hh]      + zz[32 + bl][hh];
                    zd = sz0[bl][32 + hh] + zz[bl][32 + hh] + zz[32 + bl][32 + hh];
                    zt = sz0[bl][64 + hh] + zz[bl][64 + hh] + zz[32 + bl][64 + hh];
                }
                float gate = zg + sbase[bl][hh];
                float dyn  = zd + sbase[bl][32 + hh];
                float tau  = softplusf(zt + b_tau[h]);
                float hsv  = (stage == 0) ? g_h[gi] : (g_h[gi] + Ag[gi]);
                float kd   = (sigmoidf(gate) * tanhf(dyn) - hsv) / (tau + g_leak[h] + 1e-6f);
                float dt   = x_dts[b * TT + t];
                if (stage == 0) {
                    g_k1[gi] = kd;
                    g_dA[gi] = dt * kd * (1.f / 3.f);
                } else if (stage == 1) {
                    g_k2[gi] = kd;
                    g_dB[gi] = dt * (kd - g_k1[gi] * (1.f / 3.f));
                } else if (stage == 2) {
                    g_k3[gi] = kd;
                    g_dA[gi] = dt * (g_k1[gi] - g_k2[gi] + kd);
                } else {
                    g_h[gi] = g_h[gi] + dt * (g_k1[gi] + 3.f * g_k2[gi] + 3.f * g_k3[gi] + kd) * 0.125f;
                }
            }
            gbar(gid, 16);
        }
    }

    // ===== final projection =====
    {
        int b = bid * 2 + (tid >> 8);
        int lt = tid & 255;
        if (lt < OO) {
            float acc = b_fc[lt];
#pragma unroll 8
            for (int k = 0; k < HH; k++) acc += g_h[b * HH + k] * W_fc[k * OO + lt];
            out[b * OO + lt] = acc;
        }
    }
}

// ---------------- launch ----------------
extern "C" void kernel_launch(void* const* d_in, const int* in_sizes, int n_in,
                              void* d_out, int out_size) {
    const float* x_states = (const float*)d_in[0];
    const float* x_dts    = (const float*)d_in[1];
    const float* Wq    = (const float*)d_in[2];
    const float* bq    = (const float*)d_in[3];
    const float* Wk    = (const float*)d_in[4];
    const float* bk    = (const float*)d_in[5];
    const float* Wv    = (const float*)d_in[6];
    const float* bv    = (const float*)d_in[7];
    const float* W_gd  = (const float*)d_in[8];
    const float* b_gd  = (const float*)d_in[9];
    const float* W_tau = (const float*)d_in[10];
    const float* b_tau = (const float*)d_in[11];
    const float* gleak = (const float*)d_in[12];
    const float* cm    = (const float*)d_in[13];
    const float* W_fc  = (const float*)d_in[14];
    const float* b_fc  = (const float*)d_in[15];
    float* out = (float*)d_out;

    cudaFuncSetAttribute(mega, cudaFuncAttributeMaxDynamicSharedMemorySize, SMEM_BYTES);
    mega<<<NBLK, NTHR, SMEM_BYTES>>>(x_states, x_dts, Wq, bq, Wk, bk, Wv, bv,
                                     W_gd, b_gd, W_tau, b_tau, gleak, cm,
                                     W_fc, b_fc, out);
}